// round 10
// baseline (speedup 1.0000x reference)
#include <cuda_runtime.h>
#include <cuda_bf16.h>
#include <math.h>

// DecodeSBP: per-keypoint argmax over sigmoid heatmaps.
// x: [1, 133, 512, 512] fp32.  out: [133,3] = (x*4, y*4, conf) or (-4,-4,-1).
// sigmoid monotonic -> argmax(sigmoid) == argmax; sigmoid only on the max.
//
// Round 10: 2 CTAs per keypoint, 266 CTAs x 512 threads = SINGLE wave at
// 2 CTAs/SM (266 <= 296 slots) with keypoint-aligned halves -> zero boundary
// logic, literal 64-iter batched loop (structure identical to R9's proven
// codegen: 8 groups x 8 back-to-back LDG.128, regs ~56). All 148 SMs stream
// (R1 idled 15). Merge: one 64-bit atomicMax per CTA; key =
// (monotonic float bits << 32) | ~idx -> max value, smallest index on ties
// (first occurrence). Last finishing CTA decodes + resets for graph replay.

#define KPTS   133
#define HW     (512 * 512)
#define HW4    65536                 // float4 per keypoint
#define W      512
#define SCALE  4.0f
#define CONF_THRESHOLD 0.8f

#define NT      512
#define HALVES  2
#define NBLOCKS (KPTS * HALVES)      // 266
#define HALF_V  (HW4 / HALVES)       // 32768 float4 per half
#define UB      8
#define GROUPS  (HALF_V / (NT * UB)) // 8 groups x 8 = 64 iters/thread

__device__ unsigned long long g_best[KPTS];   // zero-init: loses to any finite value
__device__ unsigned int g_count = 0;

__device__ __forceinline__ unsigned int float_to_key(float f) {
    unsigned int u = __float_as_uint(f);
    return u ^ ((unsigned int)((int)u >> 31) | 0x80000000u);
}
__device__ __forceinline__ float key_to_float(unsigned int k) {
    unsigned int u = (k & 0x80000000u) ? (k ^ 0x80000000u) : ~k;
    return __uint_as_float(u);
}

__global__ __launch_bounds__(NT, 2)
void decode_sbp_kernel(const float* __restrict__ x, float* __restrict__ out) {
    const int h = blockIdx.x;        // 0..265
    const int k = h >> 1;            // keypoint
    const int half = h & 1;
    const float4* __restrict__ p =
        reinterpret_cast<const float4*>(x + (size_t)k * HW) + half * HALF_V;

    const int tid = threadIdx.x;

    float best = -INFINITY;
    int bidx = 0;

    // 8 groups x (8 back-to-back streaming LDG.128 -> compares).
    // Per-thread indices strictly increase -> '>' keeps first occurrence.
    #pragma unroll
    for (int g = 0; g < GROUPS; g++) {
        const int base = g * (NT * UB) + tid;
        float4 v[UB];
        #pragma unroll
        for (int u = 0; u < UB; u++)
            v[u] = __ldcs(p + base + u * NT);
        #pragma unroll
        for (int u = 0; u < UB; u++) {
            const int b = (base + u * NT) << 2;   // index within this half
            if (v[u].x > best) { best = v[u].x; bidx = b;     }
            if (v[u].y > best) { best = v[u].y; bidx = b + 1; }
            if (v[u].z > best) { best = v[u].z; bidx = b + 2; }
            if (v[u].w > best) { best = v[u].w; bidx = b + 3; }
        }
    }
    bidx += half * (HALF_V << 2);    // local index within keypoint

    // 64-bit max-reducible key.
    unsigned long long key =
        ((unsigned long long)float_to_key(best) << 32) | (unsigned int)(~bidx);

    #pragma unroll
    for (int off = 16; off > 0; off >>= 1) {
        unsigned long long o = __shfl_down_sync(0xFFFFFFFFu, key, off);
        if (o > key) key = o;
    }

    __shared__ unsigned long long s_key[NT / 32];
    __shared__ int s_last;
    const int lane = tid & 31;
    const int wid  = tid >> 5;
    if (lane == 0) s_key[wid] = key;
    __syncthreads();

    if (tid == 0) {
        #pragma unroll
        for (int w = 1; w < NT / 32; w++)
            if (s_key[w] > key) key = s_key[w];
        atomicMax(&g_best[k], key);
        __threadfence();
        unsigned int old = atomicAdd(&g_count, 1u);
        s_last = (old == NBLOCKS - 1) ? 1 : 0;
    }
    __syncthreads();

    if (s_last) {
        __threadfence();
        if (tid < KPTS) {
            const unsigned long long m = g_best[tid];
            const float mv  = key_to_float((unsigned int)(m >> 32));
            const int   idx = (int)~(unsigned int)(m & 0xFFFFFFFFu);
            const float conf = 1.0f / (1.0f + __expf(-mv));
            const bool valid = conf > CONF_THRESHOLD;
            const float yy = (float)(idx / W);
            const float xx = (float)(idx % W);
            out[tid * 3 + 0] = valid ? xx * SCALE : -SCALE;
            out[tid * 3 + 1] = valid ? yy * SCALE : -SCALE;
            out[tid * 3 + 2] = valid ? conf : -1.0f;
            g_best[tid] = 0ull;      // reset for next graph replay
        }
        if (tid == 0) g_count = 0;
    }
}

extern "C" void kernel_launch(void* const* d_in, const int* in_sizes, int n_in,
                              void* d_out, int out_size) {
    const float* x = (const float*)d_in[0];
    float* out = (float*)d_out;
    decode_sbp_kernel<<<NBLOCKS, NT>>>(x, out);
}

// round 11
// speedup vs baseline: 1.0795x; 1.0795x over previous
#include <cuda_runtime.h>
#include <cuda_bf16.h>
#include <math.h>

// DecodeSBP: per-keypoint argmax over sigmoid heatmaps.  FINAL (converged).
// x: [1, 133, 512, 512] fp32.  out: [133,3] = (x*4, y*4, conf) or (-4,-4,-1).
// sigmoid monotonic -> argmax(sigmoid) == argmax; sigmoid only on the max.
//
// Ten rounds of structural search established:
//  - one CTA per keypoint (133 x 1024), literal-bound branch-free grid-stride
//    loop, direct output write is the fastest shape (74% DRAM, ~25.3us);
//  - every cross-CTA merge scheme (chunked grids, flat segments, atomicMax +
//    last-CTA decode) costs more than the 15 idle SMs it recovers;
//  - explicit load batching and occupancy changes are neutral in this shape;
//  - 5.85 TB/s ~= 85% of the measured LTS/HBM path cap: chip-level ceiling.
// Delta vs round 1: __ldcs streaming loads only (zero-reuse, evict-first).

#define KPTS 133
#define HW   (512 * 512)        // 262144 elements per keypoint
#define HW4  (HW / 4)           // 65536 float4 per keypoint
#define NTHREADS 1024
#define W 512
#define SCALE 4.0f              // INPUT_SIZE(2048) / W(512)
#define CONF_THRESHOLD 0.8f

__global__ __launch_bounds__(NTHREADS, 1)
void decode_sbp_kernel(const float* __restrict__ x, float* __restrict__ out) {
    const int k = blockIdx.x;
    const float4* __restrict__ p =
        reinterpret_cast<const float4*>(x + (size_t)k * HW);

    const int tid = threadIdx.x;

    float best = -INFINITY;
    int bidx = 0;

    // 64 iterations per thread; strictly increasing indices, so strict '>'
    // preserves the first-occurrence tie-break of jnp.argmax.
    #pragma unroll 8
    for (int i = tid; i < HW4; i += NTHREADS) {
        float4 v = __ldcs(p + i);
        const int base = i << 2;
        if (v.x > best) { best = v.x; bidx = base;     }
        if (v.y > best) { best = v.y; bidx = base + 1; }
        if (v.z > best) { best = v.z; bidx = base + 2; }
        if (v.w > best) { best = v.w; bidx = base + 3; }
    }

    // Warp reduction: max value, ties broken by smaller index (first occurrence).
    #pragma unroll
    for (int off = 16; off > 0; off >>= 1) {
        float v2 = __shfl_down_sync(0xFFFFFFFFu, best, off);
        int   i2 = __shfl_down_sync(0xFFFFFFFFu, bidx, off);
        if (v2 > best || (v2 == best && i2 < bidx)) { best = v2; bidx = i2; }
    }

    __shared__ float s_val[32];
    __shared__ int   s_idx[32];

    const int lane = tid & 31;
    const int wid  = tid >> 5;
    if (lane == 0) { s_val[wid] = best; s_idx[wid] = bidx; }
    __syncthreads();

    // Final reduce over 32 warp results in warp 0.
    if (wid == 0) {
        best = s_val[lane];
        bidx = s_idx[lane];
        #pragma unroll
        for (int off = 16; off > 0; off >>= 1) {
            float v2 = __shfl_down_sync(0xFFFFFFFFu, best, off);
            int   i2 = __shfl_down_sync(0xFFFFFFFFu, bidx, off);
            if (v2 > best || (v2 == best && i2 < bidx)) { best = v2; bidx = i2; }
        }
        if (lane == 0) {
            const float conf = 1.0f / (1.0f + __expf(-best));
            const bool valid = conf > CONF_THRESHOLD;
            const float yy = (float)(bidx / W);
            const float xx = (float)(bidx % W);
            // Reference: invalid rows are (-1,-1,-1), then x,y columns scaled
            // for ALL rows -> invalid rows become (-4,-4,-1).
            out[k * 3 + 0] = valid ? xx * SCALE : -SCALE;
            out[k * 3 + 1] = valid ? yy * SCALE : -SCALE;
            out[k * 3 + 2] = valid ? conf : -1.0f;
        }
    }
}

extern "C" void kernel_launch(void* const* d_in, const int* in_sizes, int n_in,
                              void* d_out, int out_size) {
    const float* x = (const float*)d_in[0];
    float* out = (float*)d_out;
    decode_sbp_kernel<<<KPTS, NTHREADS>>>(x, out);
}